// round 2
// baseline (speedup 1.0000x reference)
#include <cuda_runtime.h>
#include <cstdint>

#define BATCH 4
#define LSEQ  1024
#define DMODEL 1024
#define NH    16
#define DHD   64
#define BHN   (BATCH*NH)        // 64
#define PROJ_ELEMS (BATCH*NH*LSEQ*DHD)          // 4,194,304 floats (16 MB)
#define LOGIT_ELEMS ((size_t)BHN*LSEQ*LSEQ)     // 67,108,864 floats (256 MB)

// Scratch (device globals: allocation-free per harness rules)
__device__ float g_q[PROJ_ELEMS];
__device__ float g_k[PROJ_ELEMS];
__device__ float g_v[PROJ_ELEMS];
__device__ float g_ctx[PROJ_ELEMS];
__device__ float g_logits[LOGIT_ELEMS];

__device__ __forceinline__ uint32_t f2tf(float f) {
    uint32_t u;
    asm("cvt.rna.tf32.f32 %0, %1;" : "=r"(u) : "f"(f));
    return u;
}

__device__ __forceinline__ void mma8(float* c, const uint32_t* a, const uint32_t* b) {
    asm volatile(
        "mma.sync.aligned.m16n8k8.row.col.f32.tf32.tf32.f32 "
        "{%0,%1,%2,%3}, {%4,%5,%6,%7}, {%8,%9}, {%0,%1,%2,%3};"
        : "+f"(c[0]), "+f"(c[1]), "+f"(c[2]), "+f"(c[3])
        : "r"(a[0]), "r"(a[1]), "r"(a[2]), "r"(a[3]), "r"(b[0]), "r"(b[1]));
}

// Generic tf32 GEMM.
// BMODE 0: C = A * B^T, B stored [N][K]: B[n*ldb + k]
// BMODE 1: C = A * B,   B stored [K][N]: B[k*ldb + n]
// AMODE: 0 = A[r*lda + k]; 1 = A is [B,H,L,DH], logical (r=(b,l), k=(h,dh))
// CMODE: 0 = C[r*ldc + n]; 1 = C is [B,H,L,DH], logical (r=(b,l), n=(h,dh))
// EMODE: 0 = write, 1 = accumulate into existing C
template<int BM, int BN, int WGM, int WGN, int AMODE, int BMODE, int CMODE, int EMODE>
__global__ void __launch_bounds__(WGM*WGN*32) gemm_tf32(
    const float* __restrict__ A, const float* __restrict__ B,
    const float* __restrict__ bias, float* __restrict__ C,
    int K,
    long long lda, long long ldb, long long ldc,
    long long sAz, long long sBz, long long sCz,
    float scale)
{
    constexpr int BKt = 32;
    constexpr int NT  = WGM*WGN*32;
    constexpr int WM  = BM/WGM, WN = BN/WGN;
    constexpr int MI  = WM/16,  NI = WN/8;
    constexpr int AIT = BM*8/NT;                 // float4 loads per thread (A tile)
    constexpr int BIT = (BMODE==0) ? BN*8/NT : BKt*BN/4/NT;
    constexpr int BN4 = BN/4;

    __shared__ uint32_t sA[BM][BKt+4];
    __shared__ uint32_t sB[(BMODE==0)?BN:BKt][((BMODE==0)?BKt:BN)+4];

    const int tid  = threadIdx.x;
    const int lane = tid & 31;
    const int wid  = tid >> 5;
    const int wm   = (wid % WGM) * WM;
    const int wn   = (wid / WGM) * WN;
    const int z    = blockIdx.z;
    const int bm0  = blockIdx.y * BM;
    const int bn0  = blockIdx.x * BN;

    const float* Ap = A + (long long)z * sAz;
    const float* Bp = B + (long long)z * sBz;
    float*       Cp = C + (long long)z * sCz;

    float4 f4a[AIT], f4b[BIT];

    auto loadA = [&](int kt) {
        #pragma unroll
        for (int i = 0; i < AIT; i++) {
            int idx = tid + i*NT;
            int r = idx >> 3, c = (idx & 7) << 2;
            int grow = bm0 + r;
            int gk = kt*BKt + c;
            const float* p;
            if (AMODE == 0) {
                p = Ap + (long long)grow*lda + gk;
            } else {
                int b = grow >> 10, l = grow & 1023;
                int hh = gk >> 6,  dd = gk & 63;
                p = Ap + (long long)(b*NH + hh)*(LSEQ*DHD) + l*DHD + dd;
            }
            f4a[i] = *(const float4*)p;
        }
    };
    auto loadB = [&](int kt) {
        #pragma unroll
        for (int i = 0; i < BIT; i++) {
            int idx = tid + i*NT;
            if (BMODE == 0) {
                int r = idx >> 3, c = (idx & 7) << 2;   // r = n, c = k
                f4b[i] = *(const float4*)(Bp + (long long)(bn0 + r)*ldb + kt*BKt + c);
            } else {
                int r = idx / BN4, c = (idx % BN4) << 2; // r = k, c = n
                f4b[i] = *(const float4*)(Bp + (long long)(kt*BKt + r)*ldb + bn0 + c);
            }
        }
    };
    auto stsAB = [&]() {
        #pragma unroll
        for (int i = 0; i < AIT; i++) {
            int idx = tid + i*NT;
            int r = idx >> 3, c = (idx & 7) << 2;
            uint4 u = make_uint4(f2tf(f4a[i].x), f2tf(f4a[i].y), f2tf(f4a[i].z), f2tf(f4a[i].w));
            *(uint4*)&sA[r][c] = u;
        }
        #pragma unroll
        for (int i = 0; i < BIT; i++) {
            int idx = tid + i*NT;
            uint4 u = make_uint4(f2tf(f4b[i].x), f2tf(f4b[i].y), f2tf(f4b[i].z), f2tf(f4b[i].w));
            if (BMODE == 0) {
                int r = idx >> 3, c = (idx & 7) << 2;
                *(uint4*)&sB[r][c] = u;
            } else {
                int r = idx / BN4, c = (idx % BN4) << 2;
                *(uint4*)&sB[r][c] = u;
            }
        }
    };

    float acc[MI][NI][4];
    #pragma unroll
    for (int mi = 0; mi < MI; mi++)
        #pragma unroll
        for (int ni = 0; ni < NI; ni++)
            #pragma unroll
            for (int r = 0; r < 4; r++) acc[mi][ni][r] = 0.f;

    const int T = K / BKt;
    loadA(0); loadB(0);

    for (int t = 0; t < T; ++t) {
        stsAB();
        __syncthreads();
        if (t + 1 < T) { loadA(t+1); loadB(t+1); }

        #pragma unroll
        for (int kk = 0; kk < BKt; kk += 8) {
            uint32_t af[MI][4], bf[NI][2];
            #pragma unroll
            for (int mi = 0; mi < MI; mi++) {
                int r0 = wm + mi*16 + (lane >> 2);
                int c0 = kk + (lane & 3);
                af[mi][0] = sA[r0][c0];
                af[mi][1] = sA[r0 + 8][c0];
                af[mi][2] = sA[r0][c0 + 4];
                af[mi][3] = sA[r0 + 8][c0 + 4];
            }
            #pragma unroll
            for (int ni = 0; ni < NI; ni++) {
                int rn = wn + ni*8 + (lane >> 2);
                int c0 = kk + (lane & 3);
                if (BMODE == 0) {
                    bf[ni][0] = sB[rn][c0];
                    bf[ni][1] = sB[rn][c0 + 4];
                } else {
                    bf[ni][0] = sB[c0][rn];
                    bf[ni][1] = sB[c0 + 4][rn];
                }
            }
            #pragma unroll
            for (int mi = 0; mi < MI; mi++)
                #pragma unroll
                for (int ni = 0; ni < NI; ni++)
                    mma8(acc[mi][ni], af[mi], bf[ni]);
        }
        __syncthreads();
    }

    // Epilogue
    #pragma unroll
    for (int mi = 0; mi < MI; mi++) {
        #pragma unroll
        for (int ni = 0; ni < NI; ni++) {
            int mrow = bm0 + wm + mi*16 + (lane >> 2);
            int ncol = bn0 + wn + ni*8 + ((lane & 3) << 1);
            #pragma unroll
            for (int h2 = 0; h2 < 2; h2++) {
                int r = mrow + h2*8;
                float x = acc[mi][ni][h2*2 + 0];
                float y = acc[mi][ni][h2*2 + 1];
                if (bias) { x += bias[ncol]; y += bias[ncol + 1]; }
                x *= scale; y *= scale;
                long long off;
                if (CMODE == 0) {
                    off = (long long)r*ldc + ncol;
                } else {
                    int b = r >> 10, l = r & 1023;
                    int hh = ncol >> 6, dd = ncol & 63;
                    off = (long long)(b*NH + hh)*(LSEQ*DHD) + l*DHD + dd;
                }
                float2* pc = (float2*)(Cp + off);
                float2 v = make_float2(x, y);
                if (EMODE == 1) { float2 o = *pc; v.x += o.x; v.y += o.y; }
                *pc = v;
            }
        }
    }
}

// Row softmax over last dim (1024) with mask, in place.
__global__ void __launch_bounds__(256) softmax_k(
    float* __restrict__ logits, const unsigned char* __restrict__ mask)
{
    long long row = blockIdx.x;          // bh*L + q
    int bh = (int)(row >> 10);
    int q  = (int)(row & 1023);
    int b  = bh >> 4;

    float4* p = (float4*)(logits + row * LSEQ);
    const uchar4* mp = (const uchar4*)(mask + ((long long)b*LSEQ + q)*LSEQ);

    int tid = threadIdx.x, lane = tid & 31, wid = tid >> 5;
    float4 v = p[tid];
    uchar4 m = mp[tid];
    if (m.x) v.x = -10000.f;
    if (m.y) v.y = -10000.f;
    if (m.z) v.z = -10000.f;
    if (m.w) v.w = -10000.f;

    __shared__ float red[8];
    float mx = fmaxf(fmaxf(v.x, v.y), fmaxf(v.z, v.w));
    #pragma unroll
    for (int o = 16; o; o >>= 1) mx = fmaxf(mx, __shfl_xor_sync(0xffffffffu, mx, o));
    if (lane == 0) red[wid] = mx;
    __syncthreads();
    mx = red[0];
    #pragma unroll
    for (int i = 1; i < 8; i++) mx = fmaxf(mx, red[i]);
    __syncthreads();

    float4 e;
    e.x = __expf(v.x - mx); e.y = __expf(v.y - mx);
    e.z = __expf(v.z - mx); e.w = __expf(v.w - mx);
    float s = e.x + e.y + e.z + e.w;
    #pragma unroll
    for (int o = 16; o; o >>= 1) s += __shfl_xor_sync(0xffffffffu, s, o);
    if (lane == 0) red[wid] = s;
    __syncthreads();
    s = red[0];
    #pragma unroll
    for (int i = 1; i < 8; i++) s += red[i];

    float inv = 1.f / s;
    e.x *= inv; e.y *= inv; e.z *= inv; e.w *= inv;
    p[tid] = e;
}

extern "C" void kernel_launch(void* const* d_in, const int* in_sizes, int n_in,
                              void* d_out, int out_size)
{
    const float* key   = (const float*)d_in[0];
    const float* value = (const float*)d_in[1];
    const float* query = (const float*)d_in[2];
    const unsigned char* mask = (const unsigned char*)d_in[3];
    const float* rel_k = (const float*)d_in[4];
    const float* rel_v = (const float*)d_in[5];
    const float* Wk = (const float*)d_in[6];
    const float* bk = (const float*)d_in[7];
    const float* Wv = (const float*)d_in[8];
    const float* bv = (const float*)d_in[9];
    const float* Wq = (const float*)d_in[10];
    const float* bq = (const float*)d_in[11];
    const float* Wo = (const float*)d_in[12];
    const float* bo = (const float*)d_in[13];
    float* out = (float*)d_out;

    float *pq, *pk, *pv, *pctx, *plog;
    cudaGetSymbolAddress((void**)&pq,   g_q);
    cudaGetSymbolAddress((void**)&pk,   g_k);
    cudaGetSymbolAddress((void**)&pv,   g_v);
    cudaGetSymbolAddress((void**)&pctx, g_ctx);
    cudaGetSymbolAddress((void**)&plog, g_logits);

    const long long LL = (long long)LSEQ * LSEQ;      // 1,048,576
    const long long LD = (long long)LSEQ * DHD;       // 65,536

    // 1-3: QKV projections -> [B,H,L,DH] (CMODE=1 does the head-split)
    gemm_tf32<128,128,4,2,0,0,1,0><<<dim3(8,32,1), 256>>>(
        key,   Wk, bk, pk, DMODEL, DMODEL, DMODEL, 0, 0, 0, 0, 1.0f);
    gemm_tf32<128,128,4,2,0,0,1,0><<<dim3(8,32,1), 256>>>(
        value, Wv, bv, pv, DMODEL, DMODEL, DMODEL, 0, 0, 0, 0, 1.0f);
    gemm_tf32<128,128,4,2,0,0,1,0><<<dim3(8,32,1), 256>>>(
        query, Wq, bq, pq, DMODEL, DMODEL, DMODEL, 0, 0, 0, 0, 0.125f);

    // 4: QR (per q-row over 64 batch-heads): logits[bh,q,k] = Q[bh,q,:]·rel_k[q,k,:]
    gemm_tf32<64,128,2,4,0,0,0,0><<<dim3(8,1,1024), 256>>>(
        pq, rel_k, nullptr, plog, DHD,
        LD, DHD, LL,         // lda (bh stride), ldb, ldc (bh stride in C)
        DHD, LD, LSEQ,       // sAz (q*64), sBz (q*L*DH), sCz (q*1024)
        1.0f);

    // 5: QK (per batch-head): logits += Q·K^T
    gemm_tf32<128,128,4,2,0,0,0,1><<<dim3(8,8,BHN), 256>>>(
        pq, pk, nullptr, plog, DHD,
        DHD, DHD, LSEQ,
        LD, LD, LL,
        1.0f);

    // 6: masked softmax, in place
    softmax_k<<<BHN*LSEQ, 256>>>(plog, mask);

    // 7: AV (per batch-head): ctx = alpha·V   (BMODE=1: V is [L,DH] = K-major)
    gemm_tf32<128,64,4,2,0,1,0,0><<<dim3(1,8,BHN), 256>>>(
        plog, pv, nullptr, pctx, LSEQ,
        LSEQ, DHD, DHD,      // lda, ldb (k stride in V), ldc
        LL, LD, LD,
        1.0f);

    // 8: AR (per q-row): ctx += alpha[bh,q,:]·rel_v[q]   (BMODE=1: rel_v[q] is [L,DH])
    gemm_tf32<64,64,2,2,0,1,0,1><<<dim3(1,1,1024), 128>>>(
        plog, rel_v, nullptr, pctx, LSEQ,
        LL, DHD, LD,         // lda (bh stride), ldb (k stride), ldc (bh stride in C)
        LSEQ, LD, DHD,       // sAz (q*1024), sBz (q*L*DH), sCz (q*64)
        1.0f);

    // 9: out = ctx @ Wo^T + bo   (AMODE=1 reads ctx as [B,H,L,DH])
    gemm_tf32<128,128,4,2,1,0,0,0><<<dim3(8,32,1), 256>>>(
        pctx, Wo, bo, out, DMODEL,
        0, DMODEL, DMODEL,
        0, 0, 0,
        1.0f);
}

// round 4
// speedup vs baseline: 1.0331x; 1.0331x over previous
#include <cuda_runtime.h>
#include <cstdint>

#define BATCH 4
#define LSEQ  1024
#define DMODEL 1024
#define NH    16
#define DHD   64
#define BHN   (BATCH*NH)        // 64
#define PROJ_ELEMS (BATCH*NH*LSEQ*DHD)          // 4,194,304 floats (16 MB)
#define LOGIT_ELEMS ((size_t)BHN*LSEQ*LSEQ)     // 67,108,864 floats (256 MB)

// Scratch (device globals: allocation-free per harness rules)
__device__ float g_q[PROJ_ELEMS];
__device__ float g_k[PROJ_ELEMS];
__device__ float g_v[PROJ_ELEMS];
__device__ float g_ctx[PROJ_ELEMS];
__device__ float g_logits[LOGIT_ELEMS];
__device__ float g_invs[BHN*LSEQ];

__device__ __forceinline__ uint32_t f2tf(float f) {
    uint32_t u;
    asm("cvt.rna.tf32.f32 %0, %1;" : "=r"(u) : "f"(f));
    return u;
}

__device__ __forceinline__ void mma8(float* c, const uint32_t* a, const uint32_t* b) {
    asm volatile(
        "mma.sync.aligned.m16n8k8.row.col.f32.tf32.tf32.f32 "
        "{%0,%1,%2,%3}, {%4,%5,%6,%7}, {%8,%9}, {%0,%1,%2,%3};"
        : "+f"(c[0]), "+f"(c[1]), "+f"(c[2]), "+f"(c[3])
        : "r"(a[0]), "r"(a[1]), "r"(a[2]), "r"(a[3]), "r"(b[0]), "r"(b[1]));
}

// Generic tf32 GEMM.
// BMODE 0: C = A * B^T, B stored [N][K]: B[n*ldb + k]
// BMODE 1: C = A * B,   B stored [K][N]: B[k*ldb + n]
// AMODE: 0 = A[r*lda + k]; 1 = A is [B,H,L,DH], logical (r=(b,l), k=(h,dh))
// CMODE: 0 = C[r*ldc + n]; 1 = C is [B,H,L,DH], logical (r=(b,l), n=(h,dh))
// EMODE: 0 = write, 1 = accumulate, 2 = v=(acc+old)*rowscale[z*1024+r]
template<int BM, int BN, int WGM, int WGN, int AMODE, int BMODE, int CMODE, int EMODE>
__global__ void __launch_bounds__(WGM*WGN*32) gemm_tf32(
    const float* __restrict__ A, const float* __restrict__ B,
    const float* __restrict__ bias, float* __restrict__ C,
    int K,
    long long lda, long long ldb, long long ldc,
    long long sAz, long long sBz, long long sCz,
    float scale, const float* __restrict__ rowscale)
{
    constexpr int BKt = 32;
    constexpr int NT  = WGM*WGN*32;
    constexpr int WM  = BM/WGM, WN = BN/WGN;
    constexpr int MI  = WM/16,  NI = WN/8;
    constexpr int AIT = BM*8/NT;
    constexpr int BIT = (BMODE==0) ? BN*8/NT : BKt*BN/4/NT;
    constexpr int BN4 = BN/4;

    __shared__ uint32_t sA[BM][BKt+4];
    __shared__ uint32_t sB[(BMODE==0)?BN:BKt][((BMODE==0)?BKt:BN)+4];

    const int tid  = threadIdx.x;
    const int lane = tid & 31;
    const int wid  = tid >> 5;
    const int wm   = (wid % WGM) * WM;
    const int wn   = (wid / WGM) * WN;
    const int z    = blockIdx.z;
    const int bm0  = blockIdx.y * BM;
    const int bn0  = blockIdx.x * BN;

    const float* Ap = A + (long long)z * sAz;
    const float* Bp = B + (long long)z * sBz;
    float*       Cp = C + (long long)z * sCz;

    float4 f4a[AIT], f4b[BIT];

    auto loadA = [&](int kt) {
        #pragma unroll
        for (int i = 0; i < AIT; i++) {
            int idx = tid + i*NT;
            int r = idx >> 3, c = (idx & 7) << 2;
            int grow = bm0 + r;
            int gk = kt*BKt + c;
            const float* p;
            if (AMODE == 0) {
                p = Ap + (long long)grow*lda + gk;
            } else {
                int b = grow >> 10, l = grow & 1023;
                int hh = gk >> 6,  dd = gk & 63;
                p = Ap + (long long)(b*NH + hh)*(LSEQ*DHD) + l*DHD + dd;
            }
            f4a[i] = *(const float4*)p;
        }
    };
    auto loadB = [&](int kt) {
        #pragma unroll
        for (int i = 0; i < BIT; i++) {
            int idx = tid + i*NT;
            if (BMODE == 0) {
                int r = idx >> 3, c = (idx & 7) << 2;
                f4b[i] = *(const float4*)(Bp + (long long)(bn0 + r)*ldb + kt*BKt + c);
            } else {
                int r = idx / BN4, c = (idx % BN4) << 2;
                f4b[i] = *(const float4*)(Bp + (long long)(kt*BKt + r)*ldb + bn0 + c);
            }
        }
    };
    auto stsAB = [&]() {
        #pragma unroll
        for (int i = 0; i < AIT; i++) {
            int idx = tid + i*NT;
            int r = idx >> 3, c = (idx & 7) << 2;
            uint4 u = make_uint4(f2tf(f4a[i].x), f2tf(f4a[i].y), f2tf(f4a[i].z), f2tf(f4a[i].w));
            *(uint4*)&sA[r][c] = u;
        }
        #pragma unroll
        for (int i = 0; i < BIT; i++) {
            int idx = tid + i*NT;
            uint4 u = make_uint4(f2tf(f4b[i].x), f2tf(f4b[i].y), f2tf(f4b[i].z), f2tf(f4b[i].w));
            if (BMODE == 0) {
                int r = idx >> 3, c = (idx & 7) << 2;
                *(uint4*)&sB[r][c] = u;
            } else {
                int r = idx / BN4, c = (idx % BN4) << 2;
                *(uint4*)&sB[r][c] = u;
            }
        }
    };

    float acc[MI][NI][4];
    #pragma unroll
    for (int mi = 0; mi < MI; mi++)
        #pragma unroll
        for (int ni = 0; ni < NI; ni++)
            #pragma unroll
            for (int r = 0; r < 4; r++) acc[mi][ni][r] = 0.f;

    const int T = K / BKt;
    loadA(0); loadB(0);

    for (int t = 0; t < T; ++t) {
        stsAB();
        __syncthreads();
        if (t + 1 < T) { loadA(t+1); loadB(t+1); }

        #pragma unroll
        for (int kk = 0; kk < BKt; kk += 8) {
            uint32_t af[MI][4], bf[NI][2];
            #pragma unroll
            for (int mi = 0; mi < MI; mi++) {
                int r0 = wm + mi*16 + (lane >> 2);
                int c0 = kk + (lane & 3);
                af[mi][0] = sA[r0][c0];
                af[mi][1] = sA[r0 + 8][c0];
                af[mi][2] = sA[r0][c0 + 4];
                af[mi][3] = sA[r0 + 8][c0 + 4];
            }
            #pragma unroll
            for (int ni = 0; ni < NI; ni++) {
                int rn = wn + ni*8 + (lane >> 2);
                int c0 = kk + (lane & 3);
                if (BMODE == 0) {
                    bf[ni][0] = sB[rn][c0];
                    bf[ni][1] = sB[rn][c0 + 4];
                } else {
                    bf[ni][0] = sB[c0][rn];
                    bf[ni][1] = sB[c0 + 4][rn];
                }
            }
            #pragma unroll
            for (int mi = 0; mi < MI; mi++)
                #pragma unroll
                for (int ni = 0; ni < NI; ni++)
                    mma8(acc[mi][ni], af[mi], bf[ni]);
        }
        __syncthreads();
    }

    #pragma unroll
    for (int mi = 0; mi < MI; mi++) {
        #pragma unroll
        for (int ni = 0; ni < NI; ni++) {
            int mrow = bm0 + wm + mi*16 + (lane >> 2);
            int ncol = bn0 + wn + ni*8 + ((lane & 3) << 1);
            #pragma unroll
            for (int h2 = 0; h2 < 2; h2++) {
                int r = mrow + h2*8;
                float x = acc[mi][ni][h2*2 + 0];
                float y = acc[mi][ni][h2*2 + 1];
                if (bias) { x += bias[ncol]; y += bias[ncol + 1]; }
                x *= scale; y *= scale;
                long long off;
                if (CMODE == 0) {
                    off = (long long)r*ldc + ncol;
                } else {
                    int b = r >> 10, l = r & 1023;
                    int hh = ncol >> 6, dd = ncol & 63;
                    off = (long long)(b*NH + hh)*(LSEQ*DHD) + l*DHD + dd;
                }
                float2* pc = (float2*)(Cp + off);
                float2 v = make_float2(x, y);
                if (EMODE == 1) { float2 o = *pc; v.x += o.x; v.y += o.y; }
                if (EMODE == 2) {
                    float2 o = *pc;
                    float iv = rowscale[(long long)z*LSEQ + r];
                    v.x = (v.x + o.x) * iv;
                    v.y = (v.y + o.y) * iv;
                }
                *pc = v;
            }
        }
    }
}

// ---------------------------------------------------------------------------
// Pass 2: per-q fused QR + (add QK logits) + mask + max-free softmax + AR.
// Block = one q row. M = 64 batch-heads, N = 1024 keys in chunks of 128.
// Writes unnormalized alpha' in place into logits; ctx <- unnormalized AR';
// invs[bh,q] <- 1/rowsum.
// ---------------------------------------------------------------------------
#define P2_SMEM_WORDS (64*68 + 2*128*68 + 64*132 + 64)

__global__ void __launch_bounds__(256) pass2_fused(
    const float* __restrict__ Qp,     // [B,H,L,DH]
    const float* __restrict__ relk,   // [L,L,DH]
    const float* __restrict__ relv,   // [L,L,DH]
    float* __restrict__ logits,       // [BH,L,L] in: QK; out: alpha'
    const unsigned char* __restrict__ mask,  // [B,L,L]
    float* __restrict__ ctx,          // [B,H,L,DH] out: AR' (unnormalized)
    float* __restrict__ invs)         // [BH,L]
{
    extern __shared__ uint32_t sm[];
    uint32_t (*sQ)[68]   = (uint32_t(*)[68])sm;                           // 64x68
    uint32_t (*sR)[68]   = (uint32_t(*)[68])(sm + 64*68);                 // 128x68
    uint32_t (*sV)[68]   = (uint32_t(*)[68])(sm + 64*68 + 128*68);        // 128x68
    uint32_t (*sAL)[132] = (uint32_t(*)[132])(sm + 64*68 + 2*128*68);     // 64x132
    float* rsum = (float*)(sm + 64*68 + 2*128*68 + 64*132);               // 64

    const int q    = blockIdx.x;
    const int tid  = threadIdx.x;
    const int lane = tid & 31;
    const int wid  = tid >> 5;
    // QR warp tiling: 2x4 warps, WM=32, WN=32
    const int wm = (wid & 1) * 32;
    const int wn = (wid >> 1) * 32;
    // AR warp tiling: 2x4 warps, WM=32, WN=16
    const int wnA = (wid >> 1) * 16;

    // Load Q rows for this q: A[bh][d]
    #pragma unroll
    for (int i = 0; i < 4; i++) {
        int idx = tid + i*256;
        int r = idx >> 4, c = (idx & 15) << 2;
        float4 f = *(const float4*)(Qp + (long long)r*(LSEQ*DHD) + (long long)q*DHD + c);
        *(uint4*)&sQ[r][c] = make_uint4(f2tf(f.x), f2tf(f.y), f2tf(f.z), f2tf(f.w));
    }
    if (tid < 64) rsum[tid] = 0.f;

    float ctxr[2][2][4];
    #pragma unroll
    for (int mi = 0; mi < 2; mi++)
        #pragma unroll
        for (int ni = 0; ni < 2; ni++)
            #pragma unroll
            for (int r = 0; r < 4; r++) ctxr[mi][ni][r] = 0.f;
    float rs[4] = {0.f, 0.f, 0.f, 0.f};

    const float* relkq = relk + (long long)q * (LSEQ*DHD);
    const float* relvq = relv + (long long)q * (LSEQ*DHD);

    for (int kc = 0; kc < 8; kc++) {
        const int k0 = kc * 128;
        __syncthreads();   // previous chunk's MMAs done before overwriting sR/sV
        #pragma unroll
        for (int i = 0; i < 8; i++) {
            int idx = tid + i*256;
            int r = idx >> 4, c = (idx & 15) << 2;
            float4 f = *(const float4*)(relkq + (long long)(k0 + r)*DHD + c);
            *(uint4*)&sR[r][c] = make_uint4(f2tf(f.x), f2tf(f.y), f2tf(f.z), f2tf(f.w));
            float4 g = *(const float4*)(relvq + (long long)(k0 + r)*DHD + c);
            *(uint4*)&sV[r][c] = make_uint4(f2tf(g.x), f2tf(g.y), f2tf(g.z), f2tf(g.w));
        }
        __syncthreads();

        // QR MMA: S[64][128] for this chunk
        float S[2][4][4];
        #pragma unroll
        for (int mi = 0; mi < 2; mi++)
            #pragma unroll
            for (int ni = 0; ni < 4; ni++)
                #pragma unroll
                for (int r = 0; r < 4; r++) S[mi][ni][r] = 0.f;

        #pragma unroll
        for (int kk = 0; kk < 64; kk += 8) {
            uint32_t af[2][4], bf[4][2];
            const int c0 = kk + (lane & 3);
            #pragma unroll
            for (int mi = 0; mi < 2; mi++) {
                int r0 = wm + mi*16 + (lane >> 2);
                af[mi][0] = sQ[r0][c0];
                af[mi][1] = sQ[r0 + 8][c0];
                af[mi][2] = sQ[r0][c0 + 4];
                af[mi][3] = sQ[r0 + 8][c0 + 4];
            }
            #pragma unroll
            for (int ni = 0; ni < 4; ni++) {
                int rn = wn + ni*8 + (lane >> 2);
                bf[ni][0] = sR[rn][c0];
                bf[ni][1] = sR[rn][c0 + 4];
            }
            #pragma unroll
            for (int mi = 0; mi < 2; mi++)
                #pragma unroll
                for (int ni = 0; ni < 4; ni++)
                    mma8(S[mi][ni], af[mi], bf[ni]);
        }

        // add streamed QK logits, mask, exp; write alpha' (global + smem)
        #pragma unroll
        for (int mi = 0; mi < 2; mi++) {
            #pragma unroll
            for (int ni = 0; ni < 4; ni++) {
                #pragma unroll
                for (int h2 = 0; h2 < 2; h2++) {
                    int row  = wm + mi*16 + (lane >> 2) + h2*8;        // bh
                    int colL = wn + ni*8 + ((lane & 3) << 1);          // local k
                    int n_g  = k0 + colL;
                    long long goff = (long long)row*(LSEQ*LSEQ) + (long long)q*LSEQ + n_g;
                    float2 lg = *(const float2*)(logits + goff);
                    uchar2 mm = *(const uchar2*)(mask +
                        (long long)(row >> 4)*(LSEQ*LSEQ) + (long long)q*LSEQ + n_g);
                    float vx = S[mi][ni][h2*2 + 0] + lg.x;
                    float vy = S[mi][ni][h2*2 + 1] + lg.y;
                    if (mm.x) vx = -10000.f;
                    if (mm.y) vy = -10000.f;
                    float ex = __expf(vx);
                    float ey = __expf(vy);
                    rs[mi*2 + h2] += ex + ey;
                    *(float2*)(logits + goff) = make_float2(ex, ey);
                    sAL[row][colL]     = f2tf(ex);
                    sAL[row][colL + 1] = f2tf(ey);
                }
            }
        }
        __syncthreads();

        // AR MMA: ctxr += alpha'[64][128] * relv[q][k0:k0+128][64]
        #pragma unroll
        for (int kk = 0; kk < 128; kk += 8) {
            uint32_t af[2][4], bf[2][2];
            const int c0 = kk + (lane & 3);
            #pragma unroll
            for (int mi = 0; mi < 2; mi++) {
                int r0 = wm + mi*16 + (lane >> 2);
                af[mi][0] = sAL[r0][c0];
                af[mi][1] = sAL[r0 + 8][c0];
                af[mi][2] = sAL[r0][c0 + 4];
                af[mi][3] = sAL[r0 + 8][c0 + 4];
            }
            #pragma unroll
            for (int ni = 0; ni < 2; ni++) {
                int n0 = wnA + ni*8 + (lane >> 2);
                bf[ni][0] = sV[c0][n0];
                bf[ni][1] = sV[c0 + 4][n0];
            }
            #pragma unroll
            for (int mi = 0; mi < 2; mi++)
                #pragma unroll
                for (int ni = 0; ni < 2; ni++)
                    mma8(ctxr[mi][ni], af[mi], bf[ni]);
        }
    }

    // reduce row sums -> invs
    #pragma unroll
    for (int s = 0; s < 4; s++) {
        float v = rs[s];
        v += __shfl_xor_sync(0xffffffffu, v, 1);
        v += __shfl_xor_sync(0xffffffffu, v, 2);
        if ((lane & 3) == 0)
            atomicAdd(&rsum[wm + (s >> 1)*16 + (s & 1)*8 + (lane >> 2)], v);
    }
    __syncthreads();
    if (tid < 64) invs[(long long)tid*LSEQ + q] = 1.f / rsum[tid];

    // write unnormalized AR' to ctx[bh][q][d]
    #pragma unroll
    for (int mi = 0; mi < 2; mi++) {
        #pragma unroll
        for (int ni = 0; ni < 2; ni++) {
            #pragma unroll
            for (int h2 = 0; h2 < 2; h2++) {
                int row = wm + mi*16 + (lane >> 2) + h2*8;
                int col = wnA + ni*8 + ((lane & 3) << 1);
                *(float2*)(ctx + (long long)row*(LSEQ*DHD) + (long long)q*DHD + col) =
                    make_float2(ctxr[mi][ni][h2*2 + 0], ctxr[mi][ni][h2*2 + 1]);
            }
        }
    }
}

extern "C" void kernel_launch(void* const* d_in, const int* in_sizes, int n_in,
                              void* d_out, int out_size)
{
    const float* key   = (const float*)d_in[0];
    const float* value = (const float*)d_in[1];
    const float* query = (const float*)d_in[2];
    const unsigned char* mask = (const unsigned char*)d_in[3];
    const float* rel_k = (const float*)d_in[4];
    const float* rel_v = (const float*)d_in[5];
    const float* Wk = (const float*)d_in[6];
    const float* bk = (const float*)d_in[7];
    const float* Wv = (const float*)d_in[8];
    const float* bv = (const float*)d_in[9];
    const float* Wq = (const float*)d_in[10];
    const float* bq = (const float*)d_in[11];
    const float* Wo = (const float*)d_in[12];
    const float* bo = (const float*)d_in[13];
    float* out = (float*)d_out;

    float *pq, *pk, *pv, *pctx, *plog, *pinvs;
    cudaGetSymbolAddress((void**)&pq,    g_q);
    cudaGetSymbolAddress((void**)&pk,    g_k);
    cudaGetSymbolAddress((void**)&pv,    g_v);
    cudaGetSymbolAddress((void**)&pctx,  g_ctx);
    cudaGetSymbolAddress((void**)&plog,  g_logits);
    cudaGetSymbolAddress((void**)&pinvs, g_invs);

    const long long LL = (long long)LSEQ * LSEQ;
    const long long LD = (long long)LSEQ * DHD;
    const int P2_SMEM = P2_SMEM_WORDS * 4;

    static int attr_done = 0;
    if (!attr_done) {
        cudaFuncSetAttribute(pass2_fused,
            cudaFuncAttributeMaxDynamicSharedMemorySize, P2_SMEM);
        attr_done = 1;
    }

    // 1-3: QKV projections -> [B,H,L,DH]
    gemm_tf32<128,128,4,2,0,0,1,0><<<dim3(8,32,1), 256>>>(
        key,   Wk, bk, pk, DMODEL, DMODEL, DMODEL, 0, 0, 0, 0, 1.0f, nullptr);
    gemm_tf32<128,128,4,2,0,0,1,0><<<dim3(8,32,1), 256>>>(
        value, Wv, bv, pv, DMODEL, DMODEL, DMODEL, 0, 0, 0, 0, 1.0f, nullptr);
    gemm_tf32<128,128,4,2,0,0,1,0><<<dim3(8,32,1), 256>>>(
        query, Wq, bq, pq, DMODEL, DMODEL, DMODEL, 0, 0, 0, 0, 0.125f, nullptr);

    // 4: QK (per batch-head): logits = Q·K^T
    gemm_tf32<128,128,4,2,0,0,0,0><<<dim3(8,8,BHN), 256>>>(
        pq, pk, nullptr, plog, DHD,
        DHD, DHD, LSEQ,
        LD, LD, LL,
        1.0f, nullptr);

    // 5: fused QR + mask + softmax(no-max) + AR  -> alpha' in plog, AR' in pctx
    pass2_fused<<<1024, 256, P2_SMEM>>>(pq, rel_k, rel_v, plog, mask, pctx, pinvs);

    // 6: AV: ctx = (alpha'·V + AR') * inv_s   (BMODE=1, EMODE=2)
    gemm_tf32<128,64,4,2,0,1,0,2><<<dim3(1,8,BHN), 256>>>(
        plog, pv, nullptr, pctx, LSEQ,
        LSEQ, DHD, DHD,
        LL, LD, LD,
        1.0f, pinvs);

    // 7: out = ctx @ Wo^T + bo   (AMODE=1 reads ctx as [B,H,L,DH])
    gemm_tf32<128,128,4,2,1,0,0,0><<<dim3(8,32,1), 256>>>(
        pctx, Wo, bo, out, DMODEL,
        0, DMODEL, DMODEL,
        0, 0, 0,
        1.0f, nullptr);
}

// round 5
// speedup vs baseline: 1.1672x; 1.1298x over previous
#include <cuda_runtime.h>
#include <cstdint>

#define BATCH 4
#define LSEQ  1024
#define DMODEL 1024
#define NH    16
#define DHD   64
#define BHN   (BATCH*NH)        // 64
#define PROJ_ELEMS (BATCH*NH*LSEQ*DHD)          // 4,194,304 floats (16 MB)
#define LOGIT_ELEMS ((size_t)BHN*LSEQ*LSEQ)     // 67,108,864 floats (256 MB)

// Scratch (device globals: allocation-free per harness rules)
__device__ float g_q[PROJ_ELEMS];
__device__ float g_k[PROJ_ELEMS];
__device__ float g_v[PROJ_ELEMS];
__device__ float g_ctx[PROJ_ELEMS];
__device__ float g_logits[LOGIT_ELEMS];
__device__ float g_invs[BHN*LSEQ];

__device__ __forceinline__ uint32_t f2tf(float f) {
    uint32_t u;
    asm("cvt.rna.tf32.f32 %0, %1;" : "=r"(u) : "f"(f));
    return u;
}

__device__ __forceinline__ void mma8(float* c, const uint32_t* a, const uint32_t* b) {
    asm volatile(
        "mma.sync.aligned.m16n8k8.row.col.f32.tf32.tf32.f32 "
        "{%0,%1,%2,%3}, {%4,%5,%6,%7}, {%8,%9}, {%0,%1,%2,%3};"
        : "+f"(c[0]), "+f"(c[1]), "+f"(c[2]), "+f"(c[3])
        : "r"(a[0]), "r"(a[1]), "r"(a[2]), "r"(a[3]), "r"(b[0]), "r"(b[1]));
}

// Generic tf32 GEMM.
// BMODE 0: C = A * B^T, B stored [N][K]: B[n*ldb + k]
// BMODE 1: C = A * B,   B stored [K][N]: B[k*ldb + n]
// AMODE: 0 = A[r*lda + k]; 1 = A is [B,H,L,DH], logical (r=(b,l), k=(h,dh))
// CMODE: 0 = C[r*ldc + n]; 1 = C is [B,H,L,DH], logical (r=(b,l), n=(h,dh))
// EMODE: 0 = write, 1 = accumulate, 2 = v=(acc+old)*rowscale[z*1024+r]
template<int BM, int BN, int WGM, int WGN, int AMODE, int BMODE, int CMODE, int EMODE>
__global__ void __launch_bounds__(WGM*WGN*32) gemm_tf32(
    const float* __restrict__ A, const float* __restrict__ B,
    const float* __restrict__ bias, float* __restrict__ C,
    int K,
    long long lda, long long ldb, long long ldc,
    long long sAz, long long sBz, long long sCz,
    float scale, const float* __restrict__ rowscale)
{
    constexpr int BKt = 32;
    constexpr int NT  = WGM*WGN*32;
    constexpr int WM  = BM/WGM, WN = BN/WGN;
    constexpr int MI  = WM/16,  NI = WN/8;
    constexpr int AIT = BM*8/NT;
    constexpr int BIT = (BMODE==0) ? BN*8/NT : BKt*BN/4/NT;
    constexpr int BN4 = BN/4;
    constexpr int BPAD = (BMODE==0) ? 4 : 8;   // stride 72 for K-major B: bank=8c+n, conflict-free

    __shared__ uint32_t sA[BM][BKt+4];
    __shared__ uint32_t sB[(BMODE==0)?BN:BKt][((BMODE==0)?BKt:BN)+BPAD];

    const int tid  = threadIdx.x;
    const int lane = tid & 31;
    const int wid  = tid >> 5;
    const int wm   = (wid % WGM) * WM;
    const int wn   = (wid / WGM) * WN;
    const int z    = blockIdx.z;
    const int bm0  = blockIdx.y * BM;
    const int bn0  = blockIdx.x * BN;

    const float* Ap = A + (long long)z * sAz;
    const float* Bp = B + (long long)z * sBz;
    float*       Cp = C + (long long)z * sCz;

    float4 f4a[AIT], f4b[BIT];

    auto loadA = [&](int kt) {
        #pragma unroll
        for (int i = 0; i < AIT; i++) {
            int idx = tid + i*NT;
            int r = idx >> 3, c = (idx & 7) << 2;
            int grow = bm0 + r;
            int gk = kt*BKt + c;
            const float* p;
            if (AMODE == 0) {
                p = Ap + (long long)grow*lda + gk;
            } else {
                int b = grow >> 10, l = grow & 1023;
                int hh = gk >> 6,  dd = gk & 63;
                p = Ap + (long long)(b*NH + hh)*(LSEQ*DHD) + l*DHD + dd;
            }
            f4a[i] = *(const float4*)p;
        }
    };
    auto loadB = [&](int kt) {
        #pragma unroll
        for (int i = 0; i < BIT; i++) {
            int idx = tid + i*NT;
            if (BMODE == 0) {
                int r = idx >> 3, c = (idx & 7) << 2;
                f4b[i] = *(const float4*)(Bp + (long long)(bn0 + r)*ldb + kt*BKt + c);
            } else {
                int r = idx / BN4, c = (idx % BN4) << 2;
                f4b[i] = *(const float4*)(Bp + (long long)(kt*BKt + r)*ldb + bn0 + c);
            }
        }
    };
    auto stsAB = [&]() {
        #pragma unroll
        for (int i = 0; i < AIT; i++) {
            int idx = tid + i*NT;
            int r = idx >> 3, c = (idx & 7) << 2;
            uint4 u = make_uint4(f2tf(f4a[i].x), f2tf(f4a[i].y), f2tf(f4a[i].z), f2tf(f4a[i].w));
            *(uint4*)&sA[r][c] = u;
        }
        #pragma unroll
        for (int i = 0; i < BIT; i++) {
            int idx = tid + i*NT;
            uint4 u = make_uint4(f2tf(f4b[i].x), f2tf(f4b[i].y), f2tf(f4b[i].z), f2tf(f4b[i].w));
            if (BMODE == 0) {
                int r = idx >> 3, c = (idx & 7) << 2;
                *(uint4*)&sB[r][c] = u;
            } else {
                int r = idx / BN4, c = (idx % BN4) << 2;
                *(uint4*)&sB[r][c] = u;
            }
        }
    };

    float acc[MI][NI][4];
    #pragma unroll
    for (int mi = 0; mi < MI; mi++)
        #pragma unroll
        for (int ni = 0; ni < NI; ni++)
            #pragma unroll
            for (int r = 0; r < 4; r++) acc[mi][ni][r] = 0.f;

    const int T = K / BKt;
    loadA(0); loadB(0);

    for (int t = 0; t < T; ++t) {
        stsAB();
        __syncthreads();
        if (t + 1 < T) { loadA(t+1); loadB(t+1); }

        #pragma unroll
        for (int kk = 0; kk < BKt; kk += 8) {
            uint32_t af[MI][4], bf[NI][2];
            #pragma unroll
            for (int mi = 0; mi < MI; mi++) {
                int r0 = wm + mi*16 + (lane >> 2);
                int c0 = kk + (lane & 3);
                af[mi][0] = sA[r0][c0];
                af[mi][1] = sA[r0 + 8][c0];
                af[mi][2] = sA[r0][c0 + 4];
                af[mi][3] = sA[r0 + 8][c0 + 4];
            }
            #pragma unroll
            for (int ni = 0; ni < NI; ni++) {
                int rn = wn + ni*8 + (lane >> 2);
                int c0 = kk + (lane & 3);
                if (BMODE == 0) {
                    bf[ni][0] = sB[rn][c0];
                    bf[ni][1] = sB[rn][c0 + 4];
                } else {
                    bf[ni][0] = sB[c0][rn];
                    bf[ni][1] = sB[c0 + 4][rn];
                }
            }
            #pragma unroll
            for (int mi = 0; mi < MI; mi++)
                #pragma unroll
                for (int ni = 0; ni < NI; ni++)
                    mma8(acc[mi][ni], af[mi], bf[ni]);
        }
        __syncthreads();
    }

    #pragma unroll
    for (int mi = 0; mi < MI; mi++) {
        #pragma unroll
        for (int ni = 0; ni < NI; ni++) {
            int mrow = bm0 + wm + mi*16 + (lane >> 2);
            int ncol = bn0 + wn + ni*8 + ((lane & 3) << 1);
            #pragma unroll
            for (int h2 = 0; h2 < 2; h2++) {
                int r = mrow + h2*8;
                float x = acc[mi][ni][h2*2 + 0];
                float y = acc[mi][ni][h2*2 + 1];
                if (bias) { x += bias[ncol]; y += bias[ncol + 1]; }
                x *= scale; y *= scale;
                long long off;
                if (CMODE == 0) {
                    off = (long long)r*ldc + ncol;
                } else {
                    int b = r >> 10, l = r & 1023;
                    int hh = ncol >> 6, dd = ncol & 63;
                    off = (long long)(b*NH + hh)*(LSEQ*DHD) + l*DHD + dd;
                }
                float2* pc = (float2*)(Cp + off);
                float2 v = make_float2(x, y);
                if (EMODE == 1) { float2 o = *pc; v.x += o.x; v.y += o.y; }
                if (EMODE == 2) {
                    float2 o = *pc;
                    float iv = rowscale[(long long)z*LSEQ + r];
                    v.x = (v.x + o.x) * iv;
                    v.y = (v.y + o.y) * iv;
                }
                *pc = v;
            }
        }
    }
}

// ---------------------------------------------------------------------------
// Pass 2 (512 threads): per-q fused QR + (add QK logits) + mask + max-free
// softmax + AR, with register prefetch of next rel chunk.
// Block = one q row. M = 64 batch-heads, N = 1024 keys in chunks of 128.
// Warp tiling (16 warps): QR 4x4 (WM=16, WN=32); AR 4x4 (WM=16, WN=16).
// ---------------------------------------------------------------------------
#define SQ_STRIDE 68
#define SR_STRIDE 68
#define SV_STRIDE 72
#define SAL_STRIDE 132
#define P2_SMEM_WORDS (64*SQ_STRIDE + 128*SR_STRIDE + 128*SV_STRIDE + 64*SAL_STRIDE + 64)

__global__ void __launch_bounds__(512) pass2_fused(
    const float* __restrict__ Qp,     // [B,H,L,DH]
    const float* __restrict__ relk,   // [L,L,DH]
    const float* __restrict__ relv,   // [L,L,DH]
    float* __restrict__ logits,       // [BH,L,L] in: QK; out: alpha'
    const unsigned char* __restrict__ mask,  // [B,L,L]
    float* __restrict__ ctx,          // [B,H,L,DH] out: AR' (unnormalized)
    float* __restrict__ invs)         // [BH,L]
{
    extern __shared__ uint32_t sm[];
    uint32_t (*sQ)[SQ_STRIDE]   = (uint32_t(*)[SQ_STRIDE])sm;
    uint32_t (*sR)[SR_STRIDE]   = (uint32_t(*)[SR_STRIDE])(sm + 64*SQ_STRIDE);
    uint32_t (*sV)[SV_STRIDE]   = (uint32_t(*)[SV_STRIDE])(sm + 64*SQ_STRIDE + 128*SR_STRIDE);
    uint32_t (*sAL)[SAL_STRIDE] = (uint32_t(*)[SAL_STRIDE])(sm + 64*SQ_STRIDE + 128*SR_STRIDE + 128*SV_STRIDE);
    float* rsum = (float*)(sm + 64*SQ_STRIDE + 128*SR_STRIDE + 128*SV_STRIDE + 64*SAL_STRIDE);

    const int q    = blockIdx.x;
    const int tid  = threadIdx.x;
    const int lane = tid & 31;
    const int wid  = tid >> 5;
    const int wm   = (wid & 3) * 16;          // QR/AR row group
    const int wn   = (wid >> 2) * 32;         // QR col group
    const int wnA  = (wid >> 2) * 16;         // AR col group

    const long long LL = (long long)LSEQ * LSEQ;

    // Load Q rows for this q: sQ[bh][d]
    #pragma unroll
    for (int i = 0; i < 2; i++) {
        int idx = tid + i*512;
        int r = idx >> 4, c = (idx & 15) << 2;
        float4 f = *(const float4*)(Qp + (long long)r*(LSEQ*DHD) + (long long)q*DHD + c);
        *(uint4*)&sQ[r][c] = make_uint4(f2tf(f.x), f2tf(f.y), f2tf(f.z), f2tf(f.w));
    }
    if (tid < 64) rsum[tid] = 0.f;

    const float* relkq = relk + (long long)q * (LSEQ*DHD);
    const float* relvq = relv + (long long)q * (LSEQ*DHD);

    float4 fR[4], fV[4];
    auto ldchunk = [&](int kc) {
        #pragma unroll
        for (int i = 0; i < 4; i++) {
            int idx = tid + i*512;
            int r = idx >> 4, c = (idx & 15) << 2;
            fR[i] = *(const float4*)(relkq + (long long)(kc*128 + r)*DHD + c);
            fV[i] = *(const float4*)(relvq + (long long)(kc*128 + r)*DHD + c);
        }
    };
    auto stchunk = [&]() {
        #pragma unroll
        for (int i = 0; i < 4; i++) {
            int idx = tid + i*512;
            int r = idx >> 4, c = (idx & 15) << 2;
            *(uint4*)&sR[r][c] = make_uint4(f2tf(fR[i].x), f2tf(fR[i].y), f2tf(fR[i].z), f2tf(fR[i].w));
            *(uint4*)&sV[r][c] = make_uint4(f2tf(fV[i].x), f2tf(fV[i].y), f2tf(fV[i].z), f2tf(fV[i].w));
        }
    };

    float ctxr[2][4];
    #pragma unroll
    for (int ni = 0; ni < 2; ni++)
        #pragma unroll
        for (int r = 0; r < 4; r++) ctxr[ni][r] = 0.f;
    float rs[2] = {0.f, 0.f};

    ldchunk(0);

    for (int kc = 0; kc < 8; kc++) {
        const int k0 = kc * 128;
        __syncthreads();                  // prev AR MMA done reading sR/sV/sAL
        stchunk();
        __syncthreads();
        if (kc + 1 < 8) ldchunk(kc + 1);  // prefetch next chunk (in flight below)

        // hoist logits + mask loads (overlap with QR MMA)
        const int rowb = wm + (lane >> 2);
        float2 lg[4][2];
        uchar2 mm[4][2];
        #pragma unroll
        for (int ni = 0; ni < 4; ni++) {
            int n_g = k0 + wn + ni*8 + ((lane & 3) << 1);
            #pragma unroll
            for (int h2 = 0; h2 < 2; h2++) {
                int row = rowb + h2*8;
                lg[ni][h2] = *(const float2*)(logits + (long long)row*LL + (long long)q*LSEQ + n_g);
                mm[ni][h2] = *(const uchar2*)(mask + (long long)(row >> 4)*LL + (long long)q*LSEQ + n_g);
            }
        }

        // QR MMA: S[64][128] chunk
        float S[4][4];
        #pragma unroll
        for (int ni = 0; ni < 4; ni++)
            #pragma unroll
            for (int r = 0; r < 4; r++) S[ni][r] = 0.f;

        #pragma unroll
        for (int kk = 0; kk < 64; kk += 8) {
            uint32_t af[4], bf[4][2];
            const int c0 = kk + (lane & 3);
            af[0] = sQ[rowb][c0];
            af[1] = sQ[rowb + 8][c0];
            af[2] = sQ[rowb][c0 + 4];
            af[3] = sQ[rowb + 8][c0 + 4];
            #pragma unroll
            for (int ni = 0; ni < 4; ni++) {
                int rn = wn + ni*8 + (lane >> 2);
                bf[ni][0] = sR[rn][c0];
                bf[ni][1] = sR[rn][c0 + 4];
            }
            #pragma unroll
            for (int ni = 0; ni < 4; ni++)
                mma8(S[ni], af, bf[ni]);
        }

        // combine + exp; write alpha' (global + smem)
        #pragma unroll
        for (int ni = 0; ni < 4; ni++) {
            int colL = wn + ni*8 + ((lane & 3) << 1);
            #pragma unroll
            for (int h2 = 0; h2 < 2; h2++) {
                int row = rowb + h2*8;
                float vx = S[ni][h2*2 + 0] + lg[ni][h2].x;
                float vy = S[ni][h2*2 + 1] + lg[ni][h2].y;
                if (mm[ni][h2].x) vx = -10000.f;
                if (mm[ni][h2].y) vy = -10000.f;
                float ex = __expf(vx);
                float ey = __expf(vy);
                rs[h2] += ex + ey;
                *(float2*)(logits + (long long)row*LL + (long long)q*LSEQ + k0 + colL) =
                    make_float2(ex, ey);
                sAL[row][colL]     = f2tf(ex);
                sAL[row][colL + 1] = f2tf(ey);
            }
        }
        __syncthreads();

        // AR MMA: ctxr += alpha'[64][128] * relv[q][k0:k0+128][:]
        #pragma unroll
        for (int kk = 0; kk < 128; kk += 8) {
            uint32_t af[4], bf[2][2];
            const int c0 = kk + (lane & 3);
            af[0] = sAL[rowb][c0];
            af[1] = sAL[rowb + 8][c0];
            af[2] = sAL[rowb][c0 + 4];
            af[3] = sAL[rowb + 8][c0 + 4];
            #pragma unroll
            for (int ni = 0; ni < 2; ni++) {
                int n0 = wnA + ni*8 + (lane >> 2);
                bf[ni][0] = sV[c0][n0];
                bf[ni][1] = sV[c0 + 4][n0];
            }
            #pragma unroll
            for (int ni = 0; ni < 2; ni++)
                mma8(ctxr[ni], af, bf[ni]);
        }
    }

    // reduce row sums -> invs
    #pragma unroll
    for (int h2 = 0; h2 < 2; h2++) {
        float v = rs[h2];
        v += __shfl_xor_sync(0xffffffffu, v, 1);
        v += __shfl_xor_sync(0xffffffffu, v, 2);
        if ((lane & 3) == 0)
            atomicAdd(&rsum[wm + (lane >> 2) + h2*8], v);
    }
    __syncthreads();
    if (tid < 64) invs[(long long)tid*LSEQ + q] = 1.f / rsum[tid];

    // write unnormalized AR' to ctx[bh][q][d]
    #pragma unroll
    for (int ni = 0; ni < 2; ni++) {
        #pragma unroll
        for (int h2 = 0; h2 < 2; h2++) {
            int row = wm + (lane >> 2) + h2*8;
            int col = wnA + ni*8 + ((lane & 3) << 1);
            *(float2*)(ctx + (long long)row*(LSEQ*DHD) + (long long)q*DHD + col) =
                make_float2(ctxr[ni][h2*2 + 0], ctxr[ni][h2*2 + 1]);
        }
    }
}

extern "C" void kernel_launch(void* const* d_in, const int* in_sizes, int n_in,
                              void* d_out, int out_size)
{
    const float* key   = (const float*)d_in[0];
    const float* value = (const float*)d_in[1];
    const float* query = (const float*)d_in[2];
    const unsigned char* mask = (const unsigned char*)d_in[3];
    const float* rel_k = (const float*)d_in[4];
    const float* rel_v = (const float*)d_in[5];
    const float* Wk = (const float*)d_in[6];
    const float* bk = (const float*)d_in[7];
    const float* Wv = (const float*)d_in[8];
    const float* bv = (const float*)d_in[9];
    const float* Wq = (const float*)d_in[10];
    const float* bq = (const float*)d_in[11];
    const float* Wo = (const float*)d_in[12];
    const float* bo = (const float*)d_in[13];
    float* out = (float*)d_out;

    float *pq, *pk, *pv, *pctx, *plog, *pinvs;
    cudaGetSymbolAddress((void**)&pq,    g_q);
    cudaGetSymbolAddress((void**)&pk,    g_k);
    cudaGetSymbolAddress((void**)&pv,    g_v);
    cudaGetSymbolAddress((void**)&pctx,  g_ctx);
    cudaGetSymbolAddress((void**)&plog,  g_logits);
    cudaGetSymbolAddress((void**)&pinvs, g_invs);

    const long long LL = (long long)LSEQ * LSEQ;
    const long long LD = (long long)LSEQ * DHD;
    const int P2_SMEM = P2_SMEM_WORDS * 4;

    static int attr_done = 0;
    if (!attr_done) {
        cudaFuncSetAttribute(pass2_fused,
            cudaFuncAttributeMaxDynamicSharedMemorySize, P2_SMEM);
        attr_done = 1;
    }

    // 1-3: QKV projections -> [B,H,L,DH]  (512 threads, 16 warps)
    gemm_tf32<128,128,4,4,0,0,1,0><<<dim3(8,32,1), 512>>>(
        key,   Wk, bk, pk, DMODEL, DMODEL, DMODEL, 0, 0, 0, 0, 1.0f, nullptr);
    gemm_tf32<128,128,4,4,0,0,1,0><<<dim3(8,32,1), 512>>>(
        value, Wv, bv, pv, DMODEL, DMODEL, DMODEL, 0, 0, 0, 0, 1.0f, nullptr);
    gemm_tf32<128,128,4,4,0,0,1,0><<<dim3(8,32,1), 512>>>(
        query, Wq, bq, pq, DMODEL, DMODEL, DMODEL, 0, 0, 0, 0, 0.125f, nullptr);

    // 4: QK (per batch-head): logits = Q·K^T
    gemm_tf32<128,128,4,4,0,0,0,0><<<dim3(8,8,BHN), 512>>>(
        pq, pk, nullptr, plog, DHD,
        DHD, DHD, LSEQ,
        LD, LD, LL,
        1.0f, nullptr);

    // 5: fused QR + mask + softmax(no-max) + AR  -> alpha' in plog, AR' in pctx
    pass2_fused<<<1024, 512, P2_SMEM>>>(pq, rel_k, rel_v, plog, mask, pctx, pinvs);

    // 6: AV: ctx = (alpha'·V + AR') * inv_s   (BMODE=1, EMODE=2)
    gemm_tf32<128,64,8,2,0,1,0,2><<<dim3(1,8,BHN), 512>>>(
        plog, pv, nullptr, pctx, LSEQ,
        LSEQ, DHD, DHD,
        LL, LD, LD,
        1.0f, pinvs);

    // 7: out = ctx @ Wo^T + bo   (AMODE=1 reads ctx as [B,H,L,DH])
    gemm_tf32<128,128,4,4,1,0,0,0><<<dim3(8,32,1), 512>>>(
        pctx, Wo, bo, out, DMODEL,
        0, DMODEL, DMODEL,
        0, 0, 0,
        1.0f, nullptr);
}